// round 7
// baseline (speedup 1.0000x reference)
#include <cuda_runtime.h>

// DynamicUpsamplingFilter (persistent-CTA, cross-tile pipelined):
//   x:       (4, 3, 180, 320) f32
//   filters: (4, 25, 16, 180, 320) f32
//   out:     (4, 48, 180, 320) f32
//   out[n, c*16+u, h, w] = sum_p x_pad[n, c, h+p/5-2, w+p%5-2] * filters[n, p, u, h, w]

#define NN 4
#define CC 3
#define HH 180
#define WW 320
#define UU 16
#define KH 5
#define KW 5
#define PP (KH*KW)
#define TILE_W 64
#define SROW 68                       // TILE_W + 4 halo
#define WT (WW / TILE_W)              // 5 w-tiles per row
#define NTILES (NN * HH * WT)         // 3600
#define NCTAS 592                     // 148 SMs x 4 CTAs
#define CHUNK (NTILES / NCTAS)        // 6
#define REM   (NTILES % NCTAS)        // 48

__global__ void __launch_bounds__(256, 4)
duf_kernel(const float* __restrict__ x,
           const float* __restrict__ filters,
           float* __restrict__ out) {
    __shared__ float sx[CC][KH][SROW];  // 4080 B

    const int wq = threadIdx.x & 15;    // float4 quad within tile
    const int u  = threadIdx.x >> 4;    // 0..15
    const size_t PS = (size_t)UU * HH * WW;  // p-plane stride (elements)

    // contiguous tile chunk for this CTA (tiles ordered wb fastest, then h, n)
    const int cb   = blockIdx.x;
    const int base = cb * CHUNK + (cb < REM ? cb : REM);
    const int cnt  = CHUNK + (cb < REM ? 1 : 0);

    // decode first tile + prologue prefetch of its kernel-row 0
    int tile = base;
    int wb = (tile % WT) * TILE_W;
    int r0 = tile / WT;
    int h  = r0 % HH;
    int n  = r0 / HH;
    const float* fp = filters + ((((size_t)n * PP) * UU + u) * HH + h) * WW + wb + wq * 4;

    float4 cur[KW], nxt[KW];
    #pragma unroll
    for (int j = 0; j < KW; ++j)
        cur[j] = __ldcs(reinterpret_cast<const float4*>(fp + (size_t)j * PS));

    for (int it = 0; it < cnt; ++it) {
        // ---- fill shared x tile (WAR barrier; harmless on first iteration) ----
        __syncthreads();
        for (int e = threadIdx.x; e < CC * KH * SROW; e += 256) {
            int pos = e % SROW;
            int t   = e / SROW;
            int i   = t % KH;
            int c   = t / KH;
            int col = wb + pos - 2;
            int row = h + i - 2;
            float v = 0.0f;
            if ((unsigned)col < WW && (unsigned)row < HH)
                v = x[((n * CC + c) * HH + row) * WW + col];
            sx[c][i][pos] = v;
        }
        __syncthreads();

        // next tile decode (for cross-tile prefetch)
        const bool last = (it == cnt - 1);
        const int ntile = tile + 1;
        const int nwb = (ntile % WT) * TILE_W;
        const int nr  = ntile / WT;
        const int nh  = nr % HH;
        const int nn2 = nr / HH;
        const float* nfp = filters +
            ((((size_t)nn2 * PP) * UU + u) * HH + nh) * WW + nwb + wq * 4;

        float4 acc[CC];
        #pragma unroll
        for (int c = 0; c < CC; ++c) acc[c] = make_float4(0.f, 0.f, 0.f, 0.f);

        #pragma unroll
        for (int i = 0; i < KH; ++i) {
            // prefetch: rows 1..4 of this tile, then row 0 of the NEXT tile
            if (i < KH - 1) {
                #pragma unroll
                for (int j = 0; j < KW; ++j)
                    nxt[j] = __ldcs(reinterpret_cast<const float4*>(
                        fp + (size_t)((i + 1) * KW + j) * PS));
            } else if (!last) {
                #pragma unroll
                for (int j = 0; j < KW; ++j)
                    nxt[j] = __ldcs(reinterpret_cast<const float4*>(
                        nfp + (size_t)j * PS));
            }

            #pragma unroll
            for (int c = 0; c < CC; ++c) {
                const float4 a  = *reinterpret_cast<const float4*>(&sx[c][i][wq * 4]);
                const float4 bb = *reinterpret_cast<const float4*>(&sx[c][i][wq * 4 + 4]);
                const float pr[8] = {a.x, a.y, a.z, a.w, bb.x, bb.y, bb.z, bb.w};
                #pragma unroll
                for (int j = 0; j < KW; ++j) {
                    acc[c].x = fmaf(pr[j + 0], cur[j].x, acc[c].x);
                    acc[c].y = fmaf(pr[j + 1], cur[j].y, acc[c].y);
                    acc[c].z = fmaf(pr[j + 2], cur[j].z, acc[c].z);
                    acc[c].w = fmaf(pr[j + 3], cur[j].w, acc[c].w);
                }
            }

            #pragma unroll
            for (int j = 0; j < KW; ++j) cur[j] = nxt[j];
        }

        // ---- store this tile: out[n, c*16+u, h, w0..w0+3] ----
        const int w0 = wb + wq * 4;
        #pragma unroll
        for (int c = 0; c < CC; ++c) {
            float4* optr = reinterpret_cast<float4*>(
                out + ((((size_t)n * (CC * UU)) + c * UU + u) * HH + h) * WW + w0);
            __stcs(optr, acc[c]);
        }

        // advance
        tile = ntile; wb = nwb; h = nh; n = nn2; fp = nfp;
    }
}

extern "C" void kernel_launch(void* const* d_in, const int* in_sizes, int n_in,
                              void* d_out, int out_size) {
    const float* x       = (const float*)d_in[0];
    const float* filters = (const float*)d_in[1];
    float* out           = (float*)d_out;

    duf_kernel<<<NCTAS, 256>>>(x, filters, out);
}

// round 8
// speedup vs baseline: 1.0893x; 1.0893x over previous
#include <cuda_runtime.h>

// DynamicUpsamplingFilter (barrier-free: patches read direct from L1/L2):
//   x:       (4, 3, 180, 320) f32
//   filters: (4, 25, 16, 180, 320) f32
//   out:     (4, 48, 180, 320) f32
//   out[n, c*16+u, h, w] = sum_p x_pad[n, c, h+p/5-2, w+p%5-2] * filters[n, p, u, h, w]

#define NN 4
#define CC 3
#define HH 180
#define WW 320
#define UU 16
#define KH 5
#define KW 5
#define PP (KH*KW)
#define TILE_W 64

__global__ void __launch_bounds__(256, 4)
duf_kernel(const float* __restrict__ x,
           const float* __restrict__ filters,
           float* __restrict__ out) {
    // Block: one (n, h, w-tile of 64). 256 threads = 16 u-values x 16 w-quads.
    // No shared memory, no __syncthreads(): warps are fully independent.
    const int wq = threadIdx.x & 15;
    const int u  = threadIdx.x >> 4;
    const int wb = blockIdx.x * TILE_W;
    const int h  = blockIdx.y;
    const int n  = blockIdx.z;

    const int w0 = wb + wq * 4;
    const float* fp = filters + ((((size_t)n * PP) * UU + u) * HH + h) * WW + w0;
    const size_t PS = (size_t)UU * HH * WW;  // p-plane stride (elements)

    // edge predicates (cover zero-padding exactly):
    const bool lok = (w0 >= 4);     // f0 valid (else cols w0-4..w0-1 are pad/OOB)
    const bool rok = (w0 < 316);    // f2 valid (else cols w0+4..w0+7 are pad/OOB)

    // ---- hoist kernel-row 0 filter loads: DRAM stream in flight immediately
    float4 cur[KW], nxt[KW];
    #pragma unroll
    for (int j = 0; j < KW; ++j)
        cur[j] = __ldcs(reinterpret_cast<const float4*>(fp + (size_t)j * PS));

    float4 acc[CC];
    #pragma unroll
    for (int c = 0; c < CC; ++c) acc[c] = make_float4(0.f, 0.f, 0.f, 0.f);

    const float4 z4 = make_float4(0.f, 0.f, 0.f, 0.f);

    #pragma unroll
    for (int i = 0; i < KH; ++i) {
        // prefetch filter row i+1 while row i computes
        if (i < KH - 1) {
            #pragma unroll
            for (int j = 0; j < KW; ++j)
                nxt[j] = __ldcs(reinterpret_cast<const float4*>(
                    fp + (size_t)((i + 1) * KW + j) * PS));
        }

        const int row = h + i - 2;
        const bool rvok = ((unsigned)row < HH);

        #pragma unroll
        for (int c = 0; c < CC; ++c) {
            const float* xrc = x + (((size_t)n * CC + c) * HH + row) * WW + w0;
            const float4 f0 = (rvok && lok)
                ? __ldg(reinterpret_cast<const float4*>(xrc - 4)) : z4;
            const float4 f1 = rvok
                ? __ldg(reinterpret_cast<const float4*>(xrc)) : z4;
            const float4 f2 = (rvok && rok)
                ? __ldg(reinterpret_cast<const float4*>(xrc + 4)) : z4;
            // patch window cols w0-2 .. w0+5
            const float pr[8] = {f0.z, f0.w, f1.x, f1.y, f1.z, f1.w, f2.x, f2.y};
            #pragma unroll
            for (int j = 0; j < KW; ++j) {
                acc[c].x = fmaf(pr[j + 0], cur[j].x, acc[c].x);
                acc[c].y = fmaf(pr[j + 1], cur[j].y, acc[c].y);
                acc[c].z = fmaf(pr[j + 2], cur[j].z, acc[c].z);
                acc[c].w = fmaf(pr[j + 3], cur[j].w, acc[c].w);
            }
        }

        if (i < KH - 1) {
            #pragma unroll
            for (int j = 0; j < KW; ++j) cur[j] = nxt[j];
        }
    }

    // ---- store: out[n, c*16+u, h, w0..w0+3] ----
    #pragma unroll
    for (int c = 0; c < CC; ++c) {
        float4* optr = reinterpret_cast<float4*>(
            out + ((((size_t)n * (CC * UU)) + c * UU + u) * HH + h) * WW + w0);
        __stcs(optr, acc[c]);
    }
}

extern "C" void kernel_launch(void* const* d_in, const int* in_sizes, int n_in,
                              void* d_out, int out_size) {
    const float* x       = (const float*)d_in[0];
    const float* filters = (const float*)d_in[1];
    float* out           = (float*)d_out;

    dim3 grid(WW / TILE_W, HH, NN);  // (5, 180, 4) = 3600 blocks
    dim3 block(256);
    duf_kernel<<<grid, block>>>(x, filters, out);
}

// round 9
// speedup vs baseline: 1.1596x; 1.0645x over previous
#include <cuda_runtime.h>

// DynamicUpsamplingFilter:
//   x:       (4, 3, 180, 320) f32
//   filters: (4, 25, 16, 180, 320) f32
//   out:     (4, 48, 180, 320) f32
//   out[n, c*16+u, h, w] = sum_p x_pad[n, c, h+p/5-2, w+p%5-2] * filters[n, p, u, h, w]

#define NN 4
#define CC 3
#define HH 180
#define WW 320
#define UU 16
#define KH 5
#define KW 5
#define PP (KH*KW)
#define TILE_W 64
#define SROW 68                 // TILE_W + 4 halo
#define XELEMS (CC * KH * SROW) // 1020 smem elements

__global__ void __launch_bounds__(256, 4)
duf_kernel(const float* __restrict__ x,
           const float* __restrict__ filters,
           float* __restrict__ out) {
    // Block: one (n, h, w-tile of 64). 256 threads = 16 u-values x 16 w-quads.
    __shared__ float sx[CC][KH][SROW];  // 4080 B

    const int wq = threadIdx.x & 15;
    const int u  = threadIdx.x >> 4;
    const int wb = blockIdx.x * TILE_W;
    const int h  = blockIdx.y;
    const int n  = blockIdx.z;

    const int w0 = wb + wq * 4;
    const float* fp = filters + ((((size_t)n * PP) * UU + u) * HH + h) * WW + w0;
    const size_t PS = (size_t)UU * HH * WW;  // p-plane stride (elements)

    // ---- (1) x-tile loads FIRST (L2 hits; ahead of filter misses in the
    //      L1tex FIFO so the barrier releases on x latency, not DRAM latency)
    float xv[4];
    int   xe[4];
    #pragma unroll
    for (int k = 0; k < 4; ++k) {
        const int e = threadIdx.x + k * 256;
        xe[k] = e;
        float v = 0.0f;
        if (e < XELEMS) {
            const int pos = e % SROW;
            const int t   = e / SROW;
            const int i   = t % KH;
            const int c   = t / KH;
            const int col = wb + pos - 2;
            const int row = h + i - 2;
            if ((unsigned)col < WW && (unsigned)row < HH)
                v = x[((n * CC + c) * HH + row) * WW + col];
        }
        xv[k] = v;
    }

    // ---- (2) hoist filter rows 0 AND 1: 10 LDG.128 in flight during fill
    float4 cur[KW], nxt[KW];
    #pragma unroll
    for (int j = 0; j < KW; ++j)
        cur[j] = __ldcs(reinterpret_cast<const float4*>(fp + (size_t)j * PS));
    #pragma unroll
    for (int j = 0; j < KW; ++j)
        nxt[j] = __ldcs(reinterpret_cast<const float4*>(fp + (size_t)(KW + j) * PS));

    // ---- (3) store x tile + barrier (only waits on the x loads)
    float* sflat = &sx[0][0][0];
    #pragma unroll
    for (int k = 0; k < 4; ++k)
        if (xe[k] < XELEMS) sflat[xe[k]] = xv[k];
    __syncthreads();

    float4 acc[CC];
    #pragma unroll
    for (int c = 0; c < CC; ++c) acc[c] = make_float4(0.f, 0.f, 0.f, 0.f);

    // ---- (4) steady loop: compute row i, then rotate and prefetch row i+2
    #pragma unroll
    for (int i = 0; i < KH; ++i) {
        #pragma unroll
        for (int c = 0; c < CC; ++c) {
            const float4 a = *reinterpret_cast<const float4*>(&sx[c][i][wq * 4]);
            const float4 b = *reinterpret_cast<const float4*>(&sx[c][i][wq * 4 + 4]);
            const float pr[8] = {a.x, a.y, a.z, a.w, b.x, b.y, b.z, b.w};
            #pragma unroll
            for (int j = 0; j < KW; ++j) {
                acc[c].x = fmaf(pr[j + 0], cur[j].x, acc[c].x);
                acc[c].y = fmaf(pr[j + 1], cur[j].y, acc[c].y);
                acc[c].z = fmaf(pr[j + 2], cur[j].z, acc[c].z);
                acc[c].w = fmaf(pr[j + 3], cur[j].w, acc[c].w);
            }
        }
        if (i < KH - 1) {
            #pragma unroll
            for (int j = 0; j < KW; ++j) cur[j] = nxt[j];
            if (i < KH - 2) {
                #pragma unroll
                for (int j = 0; j < KW; ++j)
                    nxt[j] = __ldcs(reinterpret_cast<const float4*>(
                        fp + (size_t)((i + 2) * KW + j) * PS));
            }
        }
    }

    // ---- store: out[n, c*16+u, h, w0..w0+3] ----
    #pragma unroll
    for (int c = 0; c < CC; ++c) {
        float4* optr = reinterpret_cast<float4*>(
            out + ((((size_t)n * (CC * UU)) + c * UU + u) * HH + h) * WW + w0);
        __stcs(optr, acc[c]);
    }
}

extern "C" void kernel_launch(void* const* d_in, const int* in_sizes, int n_in,
                              void* d_out, int out_size) {
    const float* x       = (const float*)d_in[0];
    const float* filters = (const float*)d_in[1];
    float* out           = (float*)d_out;

    dim3 grid(WW / TILE_W, HH, NN);  // (5, 180, 4) = 3600 blocks
    dim3 block(256);
    duf_kernel<<<grid, block>>>(x, filters, out);
}